// round 7
// baseline (speedup 1.0000x reference)
#include <cuda_runtime.h>
#include <cuda_fp16.h>
#include <math.h>
#include <stdint.h>

#define BB 8
#define SS 2048
#define HH 768
#define MTOT (BB*SS)   // 16384
#define NQKV 2304      // 3*HH

// ---------------- scratch (device globals) ----------------
__device__ __half g_xh[MTOT*HH];
__device__ __half g_wt[4*HH*HH];                 // W^T fp16
__device__ float  g_bqkv[NQKV];
__device__ __half g_qkv[(size_t)MTOT*NQKV];      // q | k | v packed per row
__device__ __half g_vt[(size_t)BB*HH*SS];        // v^T per batch [H][S]
__device__ __half g_sc[(size_t)BB*SS*SS];        // fp16 scores -> probs in-place
__device__ __half g_ch[MTOT*HH];
__device__ float  g_h[MTOT*HH];

// ---------------- fp16 tensor-core GEMM (NT: C = alpha*A@B^T) ----------------
#define BMH 128
#define BNH 128
#define BKH 64
#define ROWB 144                    // 64 halfs = 128B -> pad to 144B
#define TILEB (BMH*ROWB)            // 18432
#define STAGEB (2*TILEB)            // 36864
#define GSMEM (2*STAGEB)            // 73728

__device__ __forceinline__ uint32_t smem_u32(const void* p){
    uint32_t a;
    asm("{ .reg .u64 t; cvta.to.shared.u64 t, %1; cvt.u32.u64 %0, t; }" : "=r"(a) : "l"(p));
    return a;
}
__device__ __forceinline__ void cp16(uint32_t smem, const void* gmem){
    asm volatile("cp.async.ca.shared.global [%0], [%1], 16;" :: "r"(smem), "l"(gmem));
}
__device__ __forceinline__ void ldsm4(uint32_t r[4], uint32_t addr){
    asm volatile("ldmatrix.sync.aligned.m8n8.x4.shared.b16 {%0,%1,%2,%3}, [%4];"
        : "=r"(r[0]), "=r"(r[1]), "=r"(r[2]), "=r"(r[3]) : "r"(addr));
}
__device__ __forceinline__ void mma_f16(float c[4],
        uint32_t a0, uint32_t a1, uint32_t a2, uint32_t a3,
        uint32_t b0, uint32_t b1){
    asm volatile(
        "mma.sync.aligned.m16n8k16.row.col.f32.f16.f16.f32 "
        "{%0,%1,%2,%3}, {%4,%5,%6,%7}, {%8,%9}, {%0,%1,%2,%3};"
        : "+f"(c[0]), "+f"(c[1]), "+f"(c[2]), "+f"(c[3])
        : "r"(a0), "r"(a1), "r"(a2), "r"(a3), "r"(b0), "r"(b1));
}

// A: [M,ldA] row-major fp16 (K cols used). B: [N,ldB] row-major fp16 (K-major).
__global__ __launch_bounds__(256, 2)
void gemm_f16(const __half* __restrict__ A, const __half* __restrict__ B,
              const float* __restrict__ bias, const float* __restrict__ res,
              float* __restrict__ Cf, __half* __restrict__ Ch,
              int K, int ldA, int ldB, int ldC,
              long long sA, long long sB, long long sC, float alpha)
{
    extern __shared__ __align__(128) char smem[];
    const uint32_t sbase = smem_u32(smem);

    A += (size_t)blockIdx.z * sA;
    B += (size_t)blockIdx.z * sB;
    if (Cf) Cf += (size_t)blockIdx.z * sC;
    if (Ch) Ch += (size_t)blockIdx.z * sC;

    const int tid  = threadIdx.x;
    const int lane = tid & 31;
    const int warp = tid >> 5;
    const int g    = lane >> 2;
    const int tg   = lane & 3;
    const int wm   = warp & 3;      // 4 warps on M (32 rows)
    const int wn   = warp >> 2;     // 2 warps on N (64 cols)
    const int m0   = blockIdx.y * BMH;
    const int n0   = blockIdx.x * BNH;
    const int NK   = K / BKH;

    float acc[2][8][4] = {};

    // ---- fill addressing: pointer-stepped ----
    const int fr = tid >> 3;            // 0..31 base row
    const int fc = tid & 7;             // 16B column group
    const __half* gA = A + (size_t)(m0 + fr) * ldA + fc * 8;
    const __half* gB = B + (size_t)(n0 + fr) * ldB + fc * 8;
    const int aStep = 32 * ldA;         // elements per 32-row hop
    const int bStep = 32 * ldB;
    const uint32_t dA0 = sbase + fr * ROWB + fc * 16;
    const uint32_t dB0 = dA0 + TILEB;

    auto fill = [&](int buf){
        const uint32_t off = buf ? STAGEB : 0u;
        #pragma unroll
        for (int i = 0; i < 4; i++)
            cp16(dA0 + off + i * (32 * ROWB), gA + (size_t)i * aStep);
        #pragma unroll
        for (int i = 0; i < 4; i++)
            cp16(dB0 + off + i * (32 * ROWB), gB + (size_t)i * bStep);
        asm volatile("cp.async.commit_group;");
        gA += BKH; gB += BKH;
    };

    // ---- ldmatrix base addresses (per buffer) ----
    const uint32_t aOff = (uint32_t)((wm * 32 + (lane & 15)) * ROWB + ((lane >> 4) * 16));
    const uint32_t bOff = (uint32_t)(TILEB + (wn * 64 + (lane & 15)) * ROWB + ((lane >> 4) * 16));
    const uint32_t aB0 = sbase + aOff,          aB1 = sbase + STAGEB + aOff;
    const uint32_t bB0 = sbase + bOff,          bB1 = sbase + STAGEB + bOff;

    fill(0);

    for (int kt = 0; kt < NK; kt++){
        asm volatile("cp.async.wait_group 0;");
        __syncthreads();
        if (kt + 1 < NK) fill((kt + 1) & 1);

        const uint32_t aB = (kt & 1) ? aB1 : aB0;
        const uint32_t bB = (kt & 1) ? bB1 : bB0;

        // fragment double buffer: prefetch ks+1 while computing ks
        uint32_t afr[2][2][4], bfr[2][4][4];
        ldsm4(afr[0][0], aB);
        ldsm4(afr[0][1], aB + 16 * ROWB);
        #pragma unroll
        for (int pr = 0; pr < 4; pr++)
            ldsm4(bfr[0][pr], bB + pr * 16 * ROWB);

        #pragma unroll
        for (int ks = 0; ks < 4; ks++){
            const int cur = ks & 1, nxt = cur ^ 1;
            if (ks < 3){
                ldsm4(afr[nxt][0], aB + (ks + 1) * 32);
                ldsm4(afr[nxt][1], aB + 16 * ROWB + (ks + 1) * 32);
                #pragma unroll
                for (int pr = 0; pr < 4; pr++)
                    ldsm4(bfr[nxt][pr], bB + pr * 16 * ROWB + (ks + 1) * 32);
            }
            #pragma unroll
            for (int pr = 0; pr < 4; pr++){
                mma_f16(acc[0][2*pr  ], afr[cur][0][0], afr[cur][0][1], afr[cur][0][2], afr[cur][0][3], bfr[cur][pr][0], bfr[cur][pr][2]);
                mma_f16(acc[0][2*pr+1], afr[cur][0][0], afr[cur][0][1], afr[cur][0][2], afr[cur][0][3], bfr[cur][pr][1], bfr[cur][pr][3]);
                mma_f16(acc[1][2*pr  ], afr[cur][1][0], afr[cur][1][1], afr[cur][1][2], afr[cur][1][3], bfr[cur][pr][0], bfr[cur][pr][2]);
                mma_f16(acc[1][2*pr+1], afr[cur][1][0], afr[cur][1][1], afr[cur][1][2], afr[cur][1][3], bfr[cur][pr][1], bfr[cur][pr][3]);
            }
        }
    }

    // epilogue
    #pragma unroll
    for (int mt = 0; mt < 2; mt++){
        #pragma unroll
        for (int nt = 0; nt < 8; nt++){
            int row = m0 + wm * 32 + mt * 16 + g;
            int col = n0 + wn * 64 + nt * 8 + tg * 2;
            float2 v0 = make_float2(acc[mt][nt][0] * alpha, acc[mt][nt][1] * alpha);
            float2 v1 = make_float2(acc[mt][nt][2] * alpha, acc[mt][nt][3] * alpha);
            if (bias){
                float2 bb = *(const float2*)(bias + col);
                v0.x += bb.x; v0.y += bb.y; v1.x += bb.x; v1.y += bb.y;
            }
            if (res){
                float2 r0 = *(const float2*)(res + (size_t)row * ldC + col);
                float2 r1 = *(const float2*)(res + (size_t)(row + 8) * ldC + col);
                v0.x += r0.x; v0.y += r0.y; v1.x += r1.x; v1.y += r1.y;
            }
            if (Cf){
                *(float2*)(Cf + (size_t)row * ldC + col) = v0;
                *(float2*)(Cf + (size_t)(row + 8) * ldC + col) = v1;
            }
            if (Ch){
                *(__half2*)(Ch + (size_t)row * ldC + col) = __floats2half2_rn(v0.x, v0.y);
                *(__half2*)(Ch + (size_t)(row + 8) * ldC + col) = __floats2half2_rn(v1.x, v1.y);
            }
        }
    }
}

// ---------------- conversions ----------------
__global__ __launch_bounds__(256)
void f32_to_f16(const float4* __restrict__ in, __half2* __restrict__ out, int n4)
{
    int i = blockIdx.x * 256 + threadIdx.x;
    if (i >= n4) return;
    float4 v = in[i];
    out[2*i]   = __floats2half2_rn(v.x, v.y);
    out[2*i+1] = __floats2half2_rn(v.z, v.w);
}

__global__ __launch_bounds__(256)
void transpose4_w(const float* __restrict__ W0, const float* __restrict__ W1,
                  const float* __restrict__ W2, const float* __restrict__ W3,
                  __half* __restrict__ outT)
{
    __shared__ float t[32][33];
    const float* in = (blockIdx.z == 0) ? W0 : (blockIdx.z == 1) ? W1
                    : (blockIdx.z == 2) ? W2 : W3;
    __half* o = outT + (size_t)blockIdx.z * HH * HH;
    const int c0 = blockIdx.x * 32, r0 = blockIdx.y * 32;
    const int tx = threadIdx.x & 31, ty = threadIdx.x >> 5;
    #pragma unroll
    for (int i = 0; i < 4; i++)
        t[ty + 8*i][tx] = in[(size_t)(r0 + ty + 8*i) * HH + c0 + tx];
    __syncthreads();
    #pragma unroll
    for (int i = 0; i < 4; i++)
        o[(size_t)(c0 + ty + 8*i) * HH + r0 + tx] = __float2half(t[tx][ty + 8*i]);
}

__global__ __launch_bounds__(256)
void transpose_f16(const __half* __restrict__ in, __half* __restrict__ outT,
                   int R, int C, int ldIn, long long sIn, long long sOut)
{
    __shared__ __half t[32][34];
    in   += (size_t)blockIdx.z * sIn;
    outT += (size_t)blockIdx.z * sOut;
    const int c0 = blockIdx.x * 32, r0 = blockIdx.y * 32;
    const int tx = threadIdx.x & 31, ty = threadIdx.x >> 5;
    #pragma unroll
    for (int i = 0; i < 4; i++)
        t[ty + 8*i][tx] = in[(size_t)(r0 + ty + 8*i) * ldIn + c0 + tx];
    __syncthreads();
    #pragma unroll
    for (int i = 0; i < 4; i++)
        outT[(size_t)(c0 + ty + 8*i) * R + r0 + tx] = t[tx][ty + 8*i];
}

__global__ void concat_bias(const float* __restrict__ a, const float* __restrict__ b,
                            const float* __restrict__ c, float* __restrict__ out)
{
    int i = blockIdx.x * 256 + threadIdx.x;
    if (i < HH)            out[i] = a[i];
    else if (i < 2*HH)     out[i] = b[i - HH];
    else if (i < 3*HH)     out[i] = c[i - 2*HH];
}

// ---------------- XSoftmax fp16 in-place ----------------
__global__ __launch_bounds__(256)
void xsoftmax_f16(__half* __restrict__ sc, const int* __restrict__ mask)
{
    const int b = blockIdx.y;
    const int s = blockIdx.x;
    __half* row = sc + ((size_t)b * SS + s) * SS;
    const int* mrow = mask + (size_t)b * SS;
    const int tid = threadIdx.x;

    uint4 raw = ((const uint4*)row)[tid];
    __half2 hx[4];
    hx[0] = *(__half2*)&raw.x; hx[1] = *(__half2*)&raw.y;
    hx[2] = *(__half2*)&raw.z; hx[3] = *(__half2*)&raw.w;
    int4 ma = ((const int4*)mrow)[2*tid];
    int4 mb = ((const int4*)mrow)[2*tid + 1];
    int m[8] = {ma.x, ma.y, ma.z, ma.w, mb.x, mb.y, mb.z, mb.w};

    const float NEG = -3.402823466e38f;
    float x[8];
    float mx = NEG;
    #pragma unroll
    for (int j = 0; j < 4; j++){
        float2 f = __half22float2(hx[j]);
        x[2*j]   = m[2*j]   ? f.x : NEG;
        x[2*j+1] = m[2*j+1] ? f.y : NEG;
        mx = fmaxf(mx, fmaxf(x[2*j], x[2*j+1]));
    }

    __shared__ float red[256];
    red[tid] = mx; __syncthreads();
    for (int off = 128; off > 0; off >>= 1){
        if (tid < off) red[tid] = fmaxf(red[tid], red[tid + off]);
        __syncthreads();
    }
    mx = red[0]; __syncthreads();

    float sum = 0.f;
    #pragma unroll
    for (int j = 0; j < 8; j++){ float e = __expf(x[j] - mx); x[j] = e; sum += e; }
    red[tid] = sum; __syncthreads();
    for (int off = 128; off > 0; off >>= 1){
        if (tid < off) red[tid] += red[tid + off];
        __syncthreads();
    }
    const float inv = 1.0f / red[0];

    #pragma unroll
    for (int j = 0; j < 4; j++){
        float p0 = m[2*j]   ? x[2*j]   * inv : 0.0f;
        float p1 = m[2*j+1] ? x[2*j+1] * inv : 0.0f;
        hx[j] = __floats2half2_rn(p0, p1);
    }
    raw.x = *(uint32_t*)&hx[0]; raw.y = *(uint32_t*)&hx[1];
    raw.z = *(uint32_t*)&hx[2]; raw.w = *(uint32_t*)&hx[3];
    ((uint4*)row)[tid] = raw;
}

// ---------------- LayerNorm ----------------
__global__ __launch_bounds__(256)
void layernorm_kernel(const float* __restrict__ h, const float* __restrict__ gamma,
                      const float* __restrict__ beta, float* __restrict__ out)
{
    const int row = blockIdx.x;
    const float* r = h + (size_t)row * HH;
    float* o = out + (size_t)row * HH;
    const int tid = threadIdx.x;

    float v0 = r[tid], v1 = r[tid + 256], v2 = r[tid + 512];
    float s = v0 + v1 + v2;
    float ss = v0*v0 + v1*v1 + v2*v2;

    __shared__ float rs[256], rss[256];
    rs[tid] = s; rss[tid] = ss; __syncthreads();
    for (int off = 128; off > 0; off >>= 1){
        if (tid < off){ rs[tid] += rs[tid + off]; rss[tid] += rss[tid + off]; }
        __syncthreads();
    }
    const float mu = rs[0] * (1.0f / HH);
    const float var = rss[0] * (1.0f / HH) - mu * mu;
    const float rstd = rsqrtf(var + 1e-12f);

    o[tid]       = (v0 - mu) * rstd * gamma[tid]       + beta[tid];
    o[tid + 256] = (v1 - mu) * rstd * gamma[tid + 256] + beta[tid + 256];
    o[tid + 512] = (v2 - mu) * rstd * gamma[tid + 512] + beta[tid + 512];
}

// ---------------- host ----------------
extern "C" void kernel_launch(void* const* d_in, const int* in_sizes, int n_in,
                              void* d_out, int out_size)
{
    const float* X     = (const float*)d_in[0];
    const int*   mask  = (const int*)  d_in[1];
    const float* Wq    = (const float*)d_in[2];
    const float* bq    = (const float*)d_in[3];
    const float* Wk    = (const float*)d_in[4];
    const float* bk    = (const float*)d_in[5];
    const float* Wv    = (const float*)d_in[6];
    const float* bv    = (const float*)d_in[7];
    const float* Wo    = (const float*)d_in[8];
    const float* bo    = (const float*)d_in[9];
    const float* gamma = (const float*)d_in[10];
    const float* beta  = (const float*)d_in[11];
    float* out = (float*)d_out;

    __half *xh, *wt, *qkv, *vt, *sc, *ch;
    float *bqkv, *h;
    cudaGetSymbolAddress((void**)&xh,   g_xh);
    cudaGetSymbolAddress((void**)&wt,   g_wt);
    cudaGetSymbolAddress((void**)&bqkv, g_bqkv);
    cudaGetSymbolAddress((void**)&qkv,  g_qkv);
    cudaGetSymbolAddress((void**)&vt,   g_vt);
    cudaGetSymbolAddress((void**)&sc,   g_sc);
    cudaGetSymbolAddress((void**)&ch,   g_ch);
    cudaGetSymbolAddress((void**)&h,    g_h);

    static int smemSet = 0;
    if (!smemSet){
        cudaFuncSetAttribute(gemm_f16, cudaFuncAttributeMaxDynamicSharedMemorySize, GSMEM);
        smemSet = 1;
    }

    const dim3 blk(256);
    const size_t WW = (size_t)HH * HH;

    // 0) conversions
    {
        int n4 = MTOT * HH / 4;
        f32_to_f16<<<(n4 + 255)/256, blk>>>((const float4*)X, (__half2*)xh, n4);
        dim3 tg(HH/32, HH/32, 4);
        transpose4_w<<<tg, blk>>>(Wq, Wk, Wv, Wo, wt);
        concat_bias<<<(NQKV + 255)/256, blk>>>(bq, bk, bv, bqkv);
    }

    // 1) fused QKV
    {
        dim3 grid(NQKV/BNH, MTOT/BMH, 1);
        gemm_f16<<<grid, blk, GSMEM>>>(xh, wt, bqkv, nullptr, nullptr, qkv,
                                       HH, HH, HH, NQKV, 0, 0, 0, 1.0f);
    }

    // 1b) v -> v^T per batch
    {
        dim3 tg(HH/32, SS/32, BB);
        transpose_f16<<<tg, blk>>>(qkv + 2*HH, vt, SS, HH, NQKV,
                                   (long long)SS*NQKV, (long long)HH*SS);
    }

    // 2) scores = q @ k^T / sqrt(H) -> fp16
    {
        dim3 grid(SS/BNH, SS/BMH, BB);
        gemm_f16<<<grid, blk, GSMEM>>>(qkv, qkv + HH, nullptr, nullptr, nullptr, sc,
                                       HH, NQKV, NQKV, SS,
                                       (long long)SS*NQKV, (long long)SS*NQKV,
                                       (long long)SS*SS, 1.0f/sqrtf((float)HH));
    }

    // 3) masked softmax in-place
    {
        dim3 grid(SS, BB, 1);
        xsoftmax_f16<<<grid, blk>>>(sc, mask);
    }

    // 4) ctx = probs @ v -> fp16
    {
        dim3 grid(HH/BNH, SS/BMH, BB);
        gemm_f16<<<grid, blk, GSMEM>>>(sc, vt, nullptr, nullptr, nullptr, ch,
                                       SS, SS, SS, HH,
                                       (long long)SS*SS, (long long)HH*SS,
                                       (long long)SS*HH, 1.0f);
    }

    // 5) h = ctx @ Wo + bo + X -> fp32
    {
        dim3 grid(HH/BNH, MTOT/BMH, 1);
        gemm_f16<<<grid, blk, GSMEM>>>(ch, wt + 3*WW, bo, X, h, nullptr,
                                       HH, HH, HH, HH, 0, 0, 0, 1.0f);
    }

    // 6) LayerNorm -> out
    {
        dim3 grid(MTOT, 1, 1);
        layernorm_kernel<<<grid, blk>>>(h, gamma, beta, out);
    }
}

// round 8
// speedup vs baseline: 1.3043x; 1.3043x over previous
#include <cuda_runtime.h>
#include <cuda_fp16.h>
#include <math.h>
#include <stdint.h>

#define BB 8
#define SS 2048
#define HH 768
#define MTOT (BB*SS)   // 16384
#define NQKV 2304      // 3*HH

// ---------------- scratch (device globals) ----------------
__device__ __half g_xh[MTOT*HH];
__device__ __half g_wt[4*HH*HH];                 // W^T fp16
__device__ float  g_bqkv[NQKV];
__device__ __half g_qkv[(size_t)MTOT*NQKV];      // q | k | v packed per row
__device__ __half g_vt[(size_t)BB*HH*SS];        // v^T per batch [H][S]
__device__ __half g_sc[(size_t)BB*SS*SS];        // fp16 scores -> probs in-place
__device__ __half g_ch[MTOT*HH];
__device__ float  g_h[MTOT*HH];

// ---------------- fp16 tensor-core GEMM (NT: C = alpha*A@B^T) ----------------
#define BMH 128
#define BNH 128
#define BKH 64
#define ROWB 144                    // 64 halfs = 128B -> pad to 144B
#define TILEB (BMH*ROWB)            // 18432
#define STAGEB (2*TILEB)            // 36864
#define NSTG 3
#define GSMEM (NSTG*STAGEB)         // 110592

__device__ __forceinline__ uint32_t smem_u32(const void* p){
    uint32_t a;
    asm("{ .reg .u64 t; cvta.to.shared.u64 t, %1; cvt.u32.u64 %0, t; }" : "=r"(a) : "l"(p));
    return a;
}
__device__ __forceinline__ void cp16(uint32_t smem, const void* gmem){
    asm volatile("cp.async.ca.shared.global [%0], [%1], 16;" :: "r"(smem), "l"(gmem));
}
__device__ __forceinline__ void ldsm4(uint32_t r[4], uint32_t addr){
    asm volatile("ldmatrix.sync.aligned.m8n8.x4.shared.b16 {%0,%1,%2,%3}, [%4];"
        : "=r"(r[0]), "=r"(r[1]), "=r"(r[2]), "=r"(r[3]) : "r"(addr));
}
__device__ __forceinline__ void mma_f16(float c[4],
        uint32_t a0, uint32_t a1, uint32_t a2, uint32_t a3,
        uint32_t b0, uint32_t b1){
    asm volatile(
        "mma.sync.aligned.m16n8k16.row.col.f32.f16.f16.f32 "
        "{%0,%1,%2,%3}, {%4,%5,%6,%7}, {%8,%9}, {%0,%1,%2,%3};"
        : "+f"(c[0]), "+f"(c[1]), "+f"(c[2]), "+f"(c[3])
        : "r"(a0), "r"(a1), "r"(a2), "r"(a3), "r"(b0), "r"(b1));
}

// A: [M,ldA] row-major fp16 (K cols used). B: [N,ldB] row-major fp16 (K-major).
__global__ __launch_bounds__(256, 2)
void gemm_f16(const __half* __restrict__ A, const __half* __restrict__ B,
              const float* __restrict__ bias, const float* __restrict__ res,
              float* __restrict__ Cf, __half* __restrict__ Ch,
              int K, int ldA, int ldB, int ldC,
              long long sA, long long sB, long long sC, float alpha)
{
    extern __shared__ __align__(128) char smem[];
    const uint32_t sbase = smem_u32(smem);

    A += (size_t)blockIdx.z * sA;
    B += (size_t)blockIdx.z * sB;
    if (Cf) Cf += (size_t)blockIdx.z * sC;
    if (Ch) Ch += (size_t)blockIdx.z * sC;

    const int tid  = threadIdx.x;
    const int lane = tid & 31;
    const int warp = tid >> 5;
    const int g    = lane >> 2;
    const int tg   = lane & 3;
    const int wm   = warp & 3;      // 4 warps on M (32 rows)
    const int wn   = warp >> 2;     // 2 warps on N (64 cols)
    const int m0   = blockIdx.y * BMH;
    const int n0   = blockIdx.x * BNH;
    const int NK   = K / BKH;

    float acc[2][8][4] = {};

    // ---- fill addressing: pointer-stepped ----
    const int fr = tid >> 3;            // 0..31 base row
    const int fc = tid & 7;             // 16B column group
    const __half* gA = A + (size_t)(m0 + fr) * ldA + fc * 8;
    const __half* gB = B + (size_t)(n0 + fr) * ldB + fc * 8;
    const int aStep = 32 * ldA;
    const int bStep = 32 * ldB;
    const uint32_t dA0 = sbase + fr * ROWB + fc * 16;
    const uint32_t dB0 = dA0 + TILEB;

    auto fill = [&](int buf){
        const uint32_t off = (uint32_t)buf * STAGEB;
        #pragma unroll
        for (int i = 0; i < 4; i++)
            cp16(dA0 + off + i * (32 * ROWB), gA + (size_t)i * aStep);
        #pragma unroll
        for (int i = 0; i < 4; i++)
            cp16(dB0 + off + i * (32 * ROWB), gB + (size_t)i * bStep);
        asm volatile("cp.async.commit_group;");
        gA += BKH; gB += BKH;
    };

    // ---- ldmatrix base offsets ----
    const uint32_t aOff = (uint32_t)((wm * 32 + (lane & 15)) * ROWB + ((lane >> 4) * 16));
    const uint32_t bOff = (uint32_t)(TILEB + (wn * 64 + (lane & 15)) * ROWB + ((lane >> 4) * 16));

    fill(0);
    fill(1);

    int fb = 2;     // next fill buffer
    int cb = 0;     // compute buffer
    for (int kt = 0; kt < NK; kt++){
        asm volatile("cp.async.wait_group 1;");
        __syncthreads();
        if (kt + 2 < NK){
            fill(fb);
            fb = (fb + 1 == NSTG) ? 0 : fb + 1;
        }

        const uint32_t sb = sbase + (uint32_t)cb * STAGEB;
        cb = (cb + 1 == NSTG) ? 0 : cb + 1;
        const uint32_t aB = sb + aOff;
        const uint32_t bB = sb + bOff;

        #pragma unroll
        for (int ks = 0; ks < 4; ks++){
            uint32_t af0[4], af1[4], bf[4][4];
            ldsm4(af0, aB + ks * 32);
            ldsm4(af1, aB + 16 * ROWB + ks * 32);
            #pragma unroll
            for (int pr = 0; pr < 4; pr++)
                ldsm4(bf[pr], bB + pr * 16 * ROWB + ks * 32);
            #pragma unroll
            for (int pr = 0; pr < 4; pr++){
                mma_f16(acc[0][2*pr  ], af0[0], af0[1], af0[2], af0[3], bf[pr][0], bf[pr][2]);
                mma_f16(acc[0][2*pr+1], af0[0], af0[1], af0[2], af0[3], bf[pr][1], bf[pr][3]);
                mma_f16(acc[1][2*pr  ], af1[0], af1[1], af1[2], af1[3], bf[pr][0], bf[pr][2]);
                mma_f16(acc[1][2*pr+1], af1[0], af1[1], af1[2], af1[3], bf[pr][1], bf[pr][3]);
            }
        }
    }

    // epilogue
    #pragma unroll
    for (int mt = 0; mt < 2; mt++){
        #pragma unroll
        for (int nt = 0; nt < 8; nt++){
            int row = m0 + wm * 32 + mt * 16 + g;
            int col = n0 + wn * 64 + nt * 8 + tg * 2;
            float2 v0 = make_float2(acc[mt][nt][0] * alpha, acc[mt][nt][1] * alpha);
            float2 v1 = make_float2(acc[mt][nt][2] * alpha, acc[mt][nt][3] * alpha);
            if (bias){
                float2 bb = *(const float2*)(bias + col);
                v0.x += bb.x; v0.y += bb.y; v1.x += bb.x; v1.y += bb.y;
            }
            if (res){
                float2 r0 = *(const float2*)(res + (size_t)row * ldC + col);
                float2 r1 = *(const float2*)(res + (size_t)(row + 8) * ldC + col);
                v0.x += r0.x; v0.y += r0.y; v1.x += r1.x; v1.y += r1.y;
            }
            if (Cf){
                *(float2*)(Cf + (size_t)row * ldC + col) = v0;
                *(float2*)(Cf + (size_t)(row + 8) * ldC + col) = v1;
            }
            if (Ch){
                *(__half2*)(Ch + (size_t)row * ldC + col) = __floats2half2_rn(v0.x, v0.y);
                *(__half2*)(Ch + (size_t)(row + 8) * ldC + col) = __floats2half2_rn(v1.x, v1.y);
            }
        }
    }
}

// ---------------- conversions ----------------
__global__ __launch_bounds__(256)
void f32_to_f16(const float4* __restrict__ in, __half2* __restrict__ out, int n4)
{
    int i = blockIdx.x * 256 + threadIdx.x;
    if (i >= n4) return;
    float4 v = in[i];
    out[2*i]   = __floats2half2_rn(v.x, v.y);
    out[2*i+1] = __floats2half2_rn(v.z, v.w);
}

__global__ __launch_bounds__(256)
void transpose4_w(const float* __restrict__ W0, const float* __restrict__ W1,
                  const float* __restrict__ W2, const float* __restrict__ W3,
                  __half* __restrict__ outT)
{
    __shared__ float t[32][33];
    const float* in = (blockIdx.z == 0) ? W0 : (blockIdx.z == 1) ? W1
                    : (blockIdx.z == 2) ? W2 : W3;
    __half* o = outT + (size_t)blockIdx.z * HH * HH;
    const int c0 = blockIdx.x * 32, r0 = blockIdx.y * 32;
    const int tx = threadIdx.x & 31, ty = threadIdx.x >> 5;
    #pragma unroll
    for (int i = 0; i < 4; i++)
        t[ty + 8*i][tx] = in[(size_t)(r0 + ty + 8*i) * HH + c0 + tx];
    __syncthreads();
    #pragma unroll
    for (int i = 0; i < 4; i++)
        o[(size_t)(c0 + ty + 8*i) * HH + r0 + tx] = __float2half(t[tx][ty + 8*i]);
}

__global__ __launch_bounds__(256)
void transpose_f16(const __half* __restrict__ in, __half* __restrict__ outT,
                   int R, int C, int ldIn, long long sIn, long long sOut)
{
    __shared__ __half t[32][34];
    in   += (size_t)blockIdx.z * sIn;
    outT += (size_t)blockIdx.z * sOut;
    const int c0 = blockIdx.x * 32, r0 = blockIdx.y * 32;
    const int tx = threadIdx.x & 31, ty = threadIdx.x >> 5;
    #pragma unroll
    for (int i = 0; i < 4; i++)
        t[ty + 8*i][tx] = in[(size_t)(r0 + ty + 8*i) * ldIn + c0 + tx];
    __syncthreads();
    #pragma unroll
    for (int i = 0; i < 4; i++)
        outT[(size_t)(c0 + ty + 8*i) * R + r0 + tx] = t[tx][ty + 8*i];
}

__global__ void concat_bias(const float* __restrict__ a, const float* __restrict__ b,
                            const float* __restrict__ c, float* __restrict__ out)
{
    int i = blockIdx.x * 256 + threadIdx.x;
    if (i < HH)            out[i] = a[i];
    else if (i < 2*HH)     out[i] = b[i - HH];
    else if (i < 3*HH)     out[i] = c[i - 2*HH];
}

// ---------------- XSoftmax fp16 in-place ----------------
__global__ __launch_bounds__(256)
void xsoftmax_f16(__half* __restrict__ sc, const int* __restrict__ mask)
{
    const int b = blockIdx.y;
    const int s = blockIdx.x;
    __half* row = sc + ((size_t)b * SS + s) * SS;
    const int* mrow = mask + (size_t)b * SS;
    const int tid = threadIdx.x;

    uint4 raw = ((const uint4*)row)[tid];
    __half2 hx[4];
    hx[0] = *(__half2*)&raw.x; hx[1] = *(__half2*)&raw.y;
    hx[2] = *(__half2*)&raw.z; hx[3] = *(__half2*)&raw.w;
    int4 ma = ((const int4*)mrow)[2*tid];
    int4 mb = ((const int4*)mrow)[2*tid + 1];
    int m[8] = {ma.x, ma.y, ma.z, ma.w, mb.x, mb.y, mb.z, mb.w};

    const float NEG = -3.402823466e38f;
    float x[8];
    float mx = NEG;
    #pragma unroll
    for (int j = 0; j < 4; j++){
        float2 f = __half22float2(hx[j]);
        x[2*j]   = m[2*j]   ? f.x : NEG;
        x[2*j+1] = m[2*j+1] ? f.y : NEG;
        mx = fmaxf(mx, fmaxf(x[2*j], x[2*j+1]));
    }

    __shared__ float red[256];
    red[tid] = mx; __syncthreads();
    for (int off = 128; off > 0; off >>= 1){
        if (tid < off) red[tid] = fmaxf(red[tid], red[tid + off]);
        __syncthreads();
    }
    mx = red[0]; __syncthreads();

    float sum = 0.f;
    #pragma unroll
    for (int j = 0; j < 8; j++){ float e = __expf(x[j] - mx); x[j] = e; sum += e; }
    red[tid] = sum; __syncthreads();
    for (int off = 128; off > 0; off >>= 1){
        if (tid < off) red[tid] += red[tid + off];
        __syncthreads();
    }
    const float inv = 1.0f / red[0];

    #pragma unroll
    for (int j = 0; j < 4; j++){
        float p0 = m[2*j]   ? x[2*j]   * inv : 0.0f;
        float p1 = m[2*j+1] ? x[2*j+1] * inv : 0.0f;
        hx[j] = __floats2half2_rn(p0, p1);
    }
    raw.x = *(uint32_t*)&hx[0]; raw.y = *(uint32_t*)&hx[1];
    raw.z = *(uint32_t*)&hx[2]; raw.w = *(uint32_t*)&hx[3];
    ((uint4*)row)[tid] = raw;
}

// ---------------- LayerNorm ----------------
__global__ __launch_bounds__(256)
void layernorm_kernel(const float* __restrict__ h, const float* __restrict__ gamma,
                      const float* __restrict__ beta, float* __restrict__ out)
{
    const int row = blockIdx.x;
    const float* r = h + (size_t)row * HH;
    float* o = out + (size_t)row * HH;
    const int tid = threadIdx.x;

    float v0 = r[tid], v1 = r[tid + 256], v2 = r[tid + 512];
    float s = v0 + v1 + v2;
    float ss = v0*v0 + v1*v1 + v2*v2;

    __shared__ float rs[256], rss[256];
    rs[tid] = s; rss[tid] = ss; __syncthreads();
    for (int off = 128; off > 0; off >>= 1){
        if (tid < off){ rs[tid] += rs[tid + off]; rss[tid] += rss[tid + off]; }
        __syncthreads();
    }
    const float mu = rs[0] * (1.0f / HH);
    const float var = rss[0] * (1.0f / HH) - mu * mu;
    const float rstd = rsqrtf(var + 1e-12f);

    o[tid]       = (v0 - mu) * rstd * gamma[tid]       + beta[tid];
    o[tid + 256] = (v1 - mu) * rstd * gamma[tid + 256] + beta[tid + 256];
    o[tid + 512] = (v2 - mu) * rstd * gamma[tid + 512] + beta[tid + 512];
}

// ---------------- host ----------------
extern "C" void kernel_launch(void* const* d_in, const int* in_sizes, int n_in,
                              void* d_out, int out_size)
{
    const float* X     = (const float*)d_in[0];
    const int*   mask  = (const int*)  d_in[1];
    const float* Wq    = (const float*)d_in[2];
    const float* bq    = (const float*)d_in[3];
    const float* Wk    = (const float*)d_in[4];
    const float* bk    = (const float*)d_in[5];
    const float* Wv    = (const float*)d_in[6];
    const float* bv    = (const float*)d_in[7];
    const float* Wo    = (const float*)d_in[8];
    const float* bo    = (const float*)d_in[9];
    const float* gamma = (const float*)d_in[10];
    const float* beta  = (const float*)d_in[11];
    float* out = (float*)d_out;

    __half *xh, *wt, *qkv, *vt, *sc, *ch;
    float *bqkv, *h;
    cudaGetSymbolAddress((void**)&xh,   g_xh);
    cudaGetSymbolAddress((void**)&wt,   g_wt);
    cudaGetSymbolAddress((void**)&bqkv, g_bqkv);
    cudaGetSymbolAddress((void**)&qkv,  g_qkv);
    cudaGetSymbolAddress((void**)&vt,   g_vt);
    cudaGetSymbolAddress((void**)&sc,   g_sc);
    cudaGetSymbolAddress((void**)&ch,   g_ch);
    cudaGetSymbolAddress((void**)&h,    g_h);

    static int smemSet = 0;
    if (!smemSet){
        cudaFuncSetAttribute(gemm_f16, cudaFuncAttributeMaxDynamicSharedMemorySize, GSMEM);
        smemSet = 1;
    }

    const dim3 blk(256);
    const size_t WW = (size_t)HH * HH;

    // 0) conversions
    {
        int n4 = MTOT * HH / 4;
        f32_to_f16<<<(n4 + 255)/256, blk>>>((const float4*)X, (__half2*)xh, n4);
        dim3 tg(HH/32, HH/32, 4);
        transpose4_w<<<tg, blk>>>(Wq, Wk, Wv, Wo, wt);
        concat_bias<<<(NQKV + 255)/256, blk>>>(bq, bk, bv, bqkv);
    }

    // 1) fused QKV
    {
        dim3 grid(NQKV/BNH, MTOT/BMH, 1);
        gemm_f16<<<grid, blk, GSMEM>>>(xh, wt, bqkv, nullptr, nullptr, qkv,
                                       HH, HH, HH, NQKV, 0, 0, 0, 1.0f);
    }

    // 1b) v -> v^T per batch
    {
        dim3 tg(HH/32, SS/32, BB);
        transpose_f16<<<tg, blk>>>(qkv + 2*HH, vt, SS, HH, NQKV,
                                   (long long)SS*NQKV, (long long)HH*SS);
    }

    // 2) scores = q @ k^T / sqrt(H) -> fp16
    {
        dim3 grid(SS/BNH, SS/BMH, BB);
        gemm_f16<<<grid, blk, GSMEM>>>(qkv, qkv + HH, nullptr, nullptr, nullptr, sc,
                                       HH, NQKV, NQKV, SS,
                                       (long long)SS*NQKV, (long long)SS*NQKV,
                                       (long long)SS*SS, 1.0f/sqrtf((float)HH));
    }

    // 3) masked softmax in-place
    {
        dim3 grid(SS, BB, 1);
        xsoftmax_f16<<<grid, blk>>>(sc, mask);
    }

    // 4) ctx = probs @ v -> fp16
    {
        dim3 grid(HH/BNH, SS/BMH, BB);
        gemm_f16<<<grid, blk, GSMEM>>>(sc, vt, nullptr, nullptr, nullptr, ch,
                                       SS, SS, SS, HH,
                                       (long long)SS*SS, (long long)HH*SS,
                                       (long long)SS*HH, 1.0f);
    }

    // 5) h = ctx @ Wo + bo + X -> fp32
    {
        dim3 grid(HH/BNH, MTOT/BMH, 1);
        gemm_f16<<<grid, blk, GSMEM>>>(ch, wt + 3*WW, bo, X, h, nullptr,
                                       HH, HH, HH, HH, 0, 0, 0, 1.0f);
    }

    // 6) LayerNorm -> out
    {
        dim3 grid(MTOT, 1, 1);
        layernorm_kernel<<<grid, blk>>>(h, gamma, beta, out);
    }
}

// round 9
// speedup vs baseline: 1.5475x; 1.1865x over previous
#include <cuda_runtime.h>
#include <cuda_fp16.h>
#include <math.h>
#include <stdint.h>

#define BB 8
#define SS 2048
#define HH 768
#define MTOT (BB*SS)   // 16384
#define NQKV 2304      // 3*HH

// ---------------- scratch (device globals) ----------------
__device__ __half g_xh[MTOT*HH];
__device__ __half g_wt[4*HH*HH];                 // W^T fp16
__device__ float  g_bqkv[NQKV];
__device__ __half g_qkv[(size_t)MTOT*NQKV];      // q | k | v packed per row
__device__ __half g_vt[(size_t)BB*HH*SS];        // v^T per batch [H][S]
__device__ __half g_sc[(size_t)BB*SS*SS];        // fp16 scores -> probs in-place
__device__ __half g_ch[MTOT*HH];
__device__ float  g_h[MTOT*HH];

// ---------------- fp16 tensor-core GEMM (NT: C = alpha*A@B^T) ----------------
// CTA tile 128x128x64, 128 threads = 4 warps, warp tile 64x64.
#define BMH 128
#define BNH 128
#define BKH 64
#define ROWB 144                    // 64 halfs = 128B -> pad to 144B
#define TILEB (BMH*ROWB)            // 18432
#define STAGEB (2*TILEB)            // 36864
#define GSMEM (2*STAGEB)            // 73728

__device__ __forceinline__ uint32_t smem_u32(const void* p){
    uint32_t a;
    asm("{ .reg .u64 t; cvta.to.shared.u64 t, %1; cvt.u32.u64 %0, t; }" : "=r"(a) : "l"(p));
    return a;
}
__device__ __forceinline__ void cp16(uint32_t smem, const void* gmem){
    asm volatile("cp.async.ca.shared.global [%0], [%1], 16;" :: "r"(smem), "l"(gmem));
}
__device__ __forceinline__ void ldsm4(uint32_t r[4], uint32_t addr){
    asm volatile("ldmatrix.sync.aligned.m8n8.x4.shared.b16 {%0,%1,%2,%3}, [%4];"
        : "=r"(r[0]), "=r"(r[1]), "=r"(r[2]), "=r"(r[3]) : "r"(addr));
}
__device__ __forceinline__ void mma_f16(float c[4],
        uint32_t a0, uint32_t a1, uint32_t a2, uint32_t a3,
        uint32_t b0, uint32_t b1){
    asm volatile(
        "mma.sync.aligned.m16n8k16.row.col.f32.f16.f16.f32 "
        "{%0,%1,%2,%3}, {%4,%5,%6,%7}, {%8,%9}, {%0,%1,%2,%3};"
        : "+f"(c[0]), "+f"(c[1]), "+f"(c[2]), "+f"(c[3])
        : "r"(a0), "r"(a1), "r"(a2), "r"(a3), "r"(b0), "r"(b1));
}

// A: [M,ldA] row-major fp16 (K cols used). B: [N,ldB] row-major fp16 (K-major).
__global__ __launch_bounds__(128, 2)
void gemm_f16(const __half* __restrict__ A, const __half* __restrict__ B,
              const float* __restrict__ bias, const float* __restrict__ res,
              float* __restrict__ Cf, __half* __restrict__ Ch,
              int K, int ldA, int ldB, int ldC,
              long long sA, long long sB, long long sC, float alpha)
{
    extern __shared__ __align__(128) char smem[];
    const uint32_t sbase = smem_u32(smem);

    A += (size_t)blockIdx.z * sA;
    B += (size_t)blockIdx.z * sB;
    if (Cf) Cf += (size_t)blockIdx.z * sC;
    if (Ch) Ch += (size_t)blockIdx.z * sC;

    const int tid  = threadIdx.x;
    const int lane = tid & 31;
    const int warp = tid >> 5;      // 0..3
    const int g    = lane >> 2;
    const int tg   = lane & 3;
    const int wm   = warp & 1;      // 2 warps on M (64 rows each)
    const int wn   = warp >> 1;     // 2 warps on N (64 cols each)
    const int m0   = blockIdx.y * BMH;
    const int n0   = blockIdx.x * BNH;
    const int NK   = K / BKH;

    float acc[4][8][4] = {};        // mt(4 x 16 rows) x nt(8 x 8 cols) x 4

    // ---- fill addressing: 128 threads, pointer-stepped ----
    const int fr = tid >> 3;            // 0..15 base row
    const int fc = tid & 7;             // 16B column group
    const __half* gA = A + (size_t)(m0 + fr) * ldA + fc * 8;
    const __half* gB = B + (size_t)(n0 + fr) * ldB + fc * 8;
    const int aStep = 16 * ldA;
    const int bStep = 16 * ldB;
    const uint32_t dA0 = sbase + fr * ROWB + fc * 16;
    const uint32_t dB0 = dA0 + TILEB;

    auto fill = [&](int buf){
        const uint32_t off = buf ? STAGEB : 0u;
        #pragma unroll
        for (int i = 0; i < 8; i++)
            cp16(dA0 + off + i * (16 * ROWB), gA + (size_t)i * aStep);
        #pragma unroll
        for (int i = 0; i < 8; i++)
            cp16(dB0 + off + i * (16 * ROWB), gB + (size_t)i * bStep);
        asm volatile("cp.async.commit_group;");
        gA += BKH; gB += BKH;
    };

    // ---- ldmatrix base offsets ----
    const uint32_t aOff = (uint32_t)((wm * 64 + (lane & 15)) * ROWB + ((lane >> 4) * 16));
    const uint32_t bOff = (uint32_t)(TILEB + (wn * 64 + (lane & 15)) * ROWB + ((lane >> 4) * 16));

    fill(0);

    for (int kt = 0; kt < NK; kt++){
        asm volatile("cp.async.wait_group 0;");
        __syncthreads();
        if (kt + 1 < NK) fill((kt + 1) & 1);

        const uint32_t sb = sbase + (kt & 1 ? STAGEB : 0u);
        const uint32_t aB = sb + aOff;
        const uint32_t bB = sb + bOff;

        #pragma unroll
        for (int ks = 0; ks < 4; ks++){
            uint32_t af[4][4];
            #pragma unroll
            for (int mt = 0; mt < 4; mt++)
                ldsm4(af[mt], aB + mt * (16 * ROWB) + ks * 32);

            uint32_t bf[2][4];
            ldsm4(bf[0], bB + ks * 32);
            #pragma unroll
            for (int pr = 0; pr < 4; pr++){
                const int c = pr & 1;
                if (pr < 3)
                    ldsm4(bf[c ^ 1], bB + (pr + 1) * (16 * ROWB) + ks * 32);
                #pragma unroll
                for (int mt = 0; mt < 4; mt++){
                    mma_f16(acc[mt][2*pr  ], af[mt][0], af[mt][1], af[mt][2], af[mt][3], bf[c][0], bf[c][2]);
                    mma_f16(acc[mt][2*pr+1], af[mt][0], af[mt][1], af[mt][2], af[mt][3], bf[c][1], bf[c][3]);
                }
            }
        }
    }

    // epilogue: warp covers rows [wm*64, +64), cols [wn*64, +64)
    #pragma unroll
    for (int mt = 0; mt < 4; mt++){
        #pragma unroll
        for (int nt = 0; nt < 8; nt++){
            int row = m0 + wm * 64 + mt * 16 + g;
            int col = n0 + wn * 64 + nt * 8 + tg * 2;
            float2 v0 = make_float2(acc[mt][nt][0] * alpha, acc[mt][nt][1] * alpha);
            float2 v1 = make_float2(acc[mt][nt][2] * alpha, acc[mt][nt][3] * alpha);
            if (bias){
                float2 bb = *(const float2*)(bias + col);
                v0.x += bb.x; v0.y += bb.y; v1.x += bb.x; v1.y += bb.y;
            }
            if (res){
                float2 r0 = *(const float2*)(res + (size_t)row * ldC + col);
                float2 r1 = *(const float2*)(res + (size_t)(row + 8) * ldC + col);
                v0.x += r0.x; v0.y += r0.y; v1.x += r1.x; v1.y += r1.y;
            }
            if (Cf){
                *(float2*)(Cf + (size_t)row * ldC + col) = v0;
                *(float2*)(Cf + (size_t)(row + 8) * ldC + col) = v1;
            }
            if (Ch){
                *(__half2*)(Ch + (size_t)row * ldC + col) = __floats2half2_rn(v0.x, v0.y);
                *(__half2*)(Ch + (size_t)(row + 8) * ldC + col) = __floats2half2_rn(v1.x, v1.y);
            }
        }
    }
}

// ---------------- conversions ----------------
__global__ __launch_bounds__(256)
void f32_to_f16(const float4* __restrict__ in, __half2* __restrict__ out, int n4)
{
    int i = blockIdx.x * 256 + threadIdx.x;
    if (i >= n4) return;
    float4 v = in[i];
    out[2*i]   = __floats2half2_rn(v.x, v.y);
    out[2*i+1] = __floats2half2_rn(v.z, v.w);
}

__global__ __launch_bounds__(256)
void transpose4_w(const float* __restrict__ W0, const float* __restrict__ W1,
                  const float* __restrict__ W2, const float* __restrict__ W3,
                  __half* __restrict__ outT)
{
    __shared__ float t[32][33];
    const float* in = (blockIdx.z == 0) ? W0 : (blockIdx.z == 1) ? W1
                    : (blockIdx.z == 2) ? W2 : W3;
    __half* o = outT + (size_t)blockIdx.z * HH * HH;
    const int c0 = blockIdx.x * 32, r0 = blockIdx.y * 32;
    const int tx = threadIdx.x & 31, ty = threadIdx.x >> 5;
    #pragma unroll
    for (int i = 0; i < 4; i++)
        t[ty + 8*i][tx] = in[(size_t)(r0 + ty + 8*i) * HH + c0 + tx];
    __syncthreads();
    #pragma unroll
    for (int i = 0; i < 4; i++)
        o[(size_t)(c0 + ty + 8*i) * HH + r0 + tx] = __float2half(t[tx][ty + 8*i]);
}

__global__ __launch_bounds__(256)
void transpose_f16(const __half* __restrict__ in, __half* __restrict__ outT,
                   int R, int C, int ldIn, long long sIn, long long sOut)
{
    __shared__ __half t[32][34];
    in   += (size_t)blockIdx.z * sIn;
    outT += (size_t)blockIdx.z * sOut;
    const int c0 = blockIdx.x * 32, r0 = blockIdx.y * 32;
    const int tx = threadIdx.x & 31, ty = threadIdx.x >> 5;
    #pragma unroll
    for (int i = 0; i < 4; i++)
        t[ty + 8*i][tx] = in[(size_t)(r0 + ty + 8*i) * ldIn + c0 + tx];
    __syncthreads();
    #pragma unroll
    for (int i = 0; i < 4; i++)
        outT[(size_t)(c0 + ty + 8*i) * R + r0 + tx] = t[tx][ty + 8*i];
}

__global__ void concat_bias(const float* __restrict__ a, const float* __restrict__ b,
                            const float* __restrict__ c, float* __restrict__ out)
{
    int i = blockIdx.x * 256 + threadIdx.x;
    if (i < HH)            out[i] = a[i];
    else if (i < 2*HH)     out[i] = b[i - HH];
    else if (i < 3*HH)     out[i] = c[i - 2*HH];
}

// ---------------- XSoftmax fp16 in-place ----------------
__global__ __launch_bounds__(256)
void xsoftmax_f16(__half* __restrict__ sc, const int* __restrict__ mask)
{
    const int b = blockIdx.y;
    const int s = blockIdx.x;
    __half* row = sc + ((size_t)b * SS + s) * SS;
    const int* mrow = mask + (size_t)b * SS;
    const int tid = threadIdx.x;

    uint4 raw = ((const uint4*)row)[tid];
    __half2 hx[4];
    hx[0] = *(__half2*)&raw.x; hx[1] = *(__half2*)&raw.y;
    hx[2] = *(__half2*)&raw.z; hx[3] = *(__half2*)&raw.w;
    int4 ma = ((const int4*)mrow)[2*tid];
    int4 mb = ((const int4*)mrow)[2*tid + 1];
    int m[8] = {ma.x, ma.y, ma.z, ma.w, mb.x, mb.y, mb.z, mb.w};

    const float NEG = -3.402823466e38f;
    float x[8];
    float mx = NEG;
    #pragma unroll
    for (int j = 0; j < 4; j++){
        float2 f = __half22float2(hx[j]);
        x[2*j]   = m[2*j]   ? f.x : NEG;
        x[2*j+1] = m[2*j+1] ? f.y : NEG;
        mx = fmaxf(mx, fmaxf(x[2*j], x[2*j+1]));
    }

    __shared__ float red[256];
    red[tid] = mx; __syncthreads();
    for (int off = 128; off > 0; off >>= 1){
        if (tid < off) red[tid] = fmaxf(red[tid], red[tid + off]);
        __syncthreads();
    }
    mx = red[0]; __syncthreads();

    float sum = 0.f;
    #pragma unroll
    for (int j = 0; j < 8; j++){ float e = __expf(x[j] - mx); x[j] = e; sum += e; }
    red[tid] = sum; __syncthreads();
    for (int off = 128; off > 0; off >>= 1){
        if (tid < off) red[tid] += red[tid + off];
        __syncthreads();
    }
    const float inv = 1.0f / red[0];

    #pragma unroll
    for (int j = 0; j < 4; j++){
        float p0 = m[2*j]   ? x[2*j]   * inv : 0.0f;
        float p1 = m[2*j+1] ? x[2*j+1] * inv : 0.0f;
        hx[j] = __floats2half2_rn(p0, p1);
    }
    raw.x = *(uint32_t*)&hx[0]; raw.y = *(uint32_t*)&hx[1];
    raw.z = *(uint32_t*)&hx[2]; raw.w = *(uint32_t*)&hx[3];
    ((uint4*)row)[tid] = raw;
}

// ---------------- LayerNorm ----------------
__global__ __launch_bounds__(256)
void layernorm_kernel(const float* __restrict__ h, const float* __restrict__ gamma,
                      const float* __restrict__ beta, float* __restrict__ out)
{
    const int row = blockIdx.x;
    const float* r = h + (size_t)row * HH;
    float* o = out + (size_t)row * HH;
    const int tid = threadIdx.x;

    float v0 = r[tid], v1 = r[tid + 256], v2 = r[tid + 512];
    float s = v0 + v1 + v2;
    float ss = v0*v0 + v1*v1 + v2*v2;

    __shared__ float rs[256], rss[256];
    rs[tid] = s; rss[tid] = ss; __syncthreads();
    for (int off = 128; off > 0; off >>= 1){
        if (tid < off){ rs[tid] += rs[tid + off]; rss[tid] += rss[tid + off]; }
        __syncthreads();
    }
    const float mu = rs[0] * (1.0f / HH);
    const float var = rss[0] * (1.0f / HH) - mu * mu;
    const float rstd = rsqrtf(var + 1e-12f);

    o[tid]       = (v0 - mu) * rstd * gamma[tid]       + beta[tid];
    o[tid + 256] = (v1 - mu) * rstd * gamma[tid + 256] + beta[tid + 256];
    o[tid + 512] = (v2 - mu) * rstd * gamma[tid + 512] + beta[tid + 512];
}

// ---------------- host ----------------
extern "C" void kernel_launch(void* const* d_in, const int* in_sizes, int n_in,
                              void* d_out, int out_size)
{
    const float* X     = (const float*)d_in[0];
    const int*   mask  = (const int*)  d_in[1];
    const float* Wq    = (const float*)d_in[2];
    const float* bq    = (const float*)d_in[3];
    const float* Wk    = (const float*)d_in[4];
    const float* bk    = (const float*)d_in[5];
    const float* Wv    = (const float*)d_in[6];
    const float* bv    = (const float*)d_in[7];
    const float* Wo    = (const float*)d_in[8];
    const float* bo    = (const float*)d_in[9];
    const float* gamma = (const float*)d_in[10];
    const float* beta  = (const float*)d_in[11];
    float* out = (float*)d_out;

    __half *xh, *wt, *qkv, *vt, *sc, *ch;
    float *bqkv, *h;
    cudaGetSymbolAddress((void**)&xh,   g_xh);
    cudaGetSymbolAddress((void**)&wt,   g_wt);
    cudaGetSymbolAddress((void**)&bqkv, g_bqkv);
    cudaGetSymbolAddress((void**)&qkv,  g_qkv);
    cudaGetSymbolAddress((void**)&vt,   g_vt);
    cudaGetSymbolAddress((void**)&sc,   g_sc);
    cudaGetSymbolAddress((void**)&ch,   g_ch);
    cudaGetSymbolAddress((void**)&h,    g_h);

    static int smemSet = 0;
    if (!smemSet){
        cudaFuncSetAttribute(gemm_f16, cudaFuncAttributeMaxDynamicSharedMemorySize, GSMEM);
        smemSet = 1;
    }

    const dim3 blkG(128);
    const dim3 blk(256);
    const size_t WW = (size_t)HH * HH;

    // 0) conversions
    {
        int n4 = MTOT * HH / 4;
        f32_to_f16<<<(n4 + 255)/256, blk>>>((const float4*)X, (__half2*)xh, n4);
        dim3 tg(HH/32, HH/32, 4);
        transpose4_w<<<tg, blk>>>(Wq, Wk, Wv, Wo, wt);
        concat_bias<<<(NQKV + 255)/256, blk>>>(bq, bk, bv, bqkv);
    }

    // 1) fused QKV
    {
        dim3 grid(NQKV/BNH, MTOT/BMH, 1);
        gemm_f16<<<grid, blkG, GSMEM>>>(xh, wt, bqkv, nullptr, nullptr, qkv,
                                        HH, HH, HH, NQKV, 0, 0, 0, 1.0f);
    }

    // 1b) v -> v^T per batch
    {
        dim3 tg(HH/32, SS/32, BB);
        transpose_f16<<<tg, blk>>>(qkv + 2*HH, vt, SS, HH, NQKV,
                                   (long long)SS*NQKV, (long long)HH*SS);
    }

    // 2) scores = q @ k^T / sqrt(H) -> fp16
    {
        dim3 grid(SS/BNH, SS/BMH, BB);
        gemm_f16<<<grid, blkG, GSMEM>>>(qkv, qkv + HH, nullptr, nullptr, nullptr, sc,
                                        HH, NQKV, NQKV, SS,
                                        (long long)SS*NQKV, (long long)SS*NQKV,
                                        (long long)SS*SS, 1.0f/sqrtf((float)HH));
    }

    // 3) masked softmax in-place
    {
        dim3 grid(SS, BB, 1);
        xsoftmax_f16<<<grid, blk>>>(sc, mask);
    }

    // 4) ctx = probs @ v -> fp16
    {
        dim3 grid(HH/BNH, SS/BMH, BB);
        gemm_f16<<<grid, blkG, GSMEM>>>(sc, vt, nullptr, nullptr, nullptr, ch,
                                        SS, SS, SS, HH,
                                        (long long)SS*SS, (long long)HH*SS,
                                        (long long)SS*HH, 1.0f);
    }

    // 5) h = ctx @ Wo + bo + X -> fp32
    {
        dim3 grid(HH/BNH, MTOT/BMH, 1);
        gemm_f16<<<grid, blkG, GSMEM>>>(ch, wt + 3*WW, bo, X, h, nullptr,
                                        HH, HH, HH, HH, 0, 0, 0, 1.0f);
    }

    // 6) LayerNorm -> out
    {
        dim3 grid(MTOT, 1, 1);
        layernorm_kernel<<<grid, blk>>>(h, gamma, beta, out);
    }
}

// round 10
// speedup vs baseline: 1.5495x; 1.0013x over previous
#include <cuda_runtime.h>
#include <cuda_fp16.h>
#include <math.h>
#include <stdint.h>

#define BB 8
#define SS 2048
#define HH 768
#define MTOT (BB*SS)   // 16384
#define NQKV 2304      // 3*HH

// ---------------- scratch (device globals) ----------------
__device__ __half g_xh[MTOT*HH];
__device__ __half g_wt[4*HH*HH];                 // W^T fp16
__device__ float  g_bqkv[NQKV];
__device__ __half g_qkv[(size_t)MTOT*NQKV];      // q | k | v packed per row
__device__ __half g_vt[(size_t)BB*HH*SS];        // v^T per batch [H][S]
__device__ __half g_sc[(size_t)BB*SS*SS];        // fp16 scores -> probs in-place
__device__ __half g_ch[MTOT*HH];
__device__ float  g_h[MTOT*HH];

// ---------------- fp16 tensor-core GEMM (NT: C = alpha*A@B^T) ----------------
// CTA tile 128x128x64, 128 threads = 4 warps, warp tile 64x64.
#define BMH 128
#define BNH 128
#define BKH 64
#define ROWB 144                    // 64 halfs = 128B -> pad to 144B
#define TILEB (BMH*ROWB)            // 18432
#define STAGEB (2*TILEB)            // 36864
#define GSMEM (2*STAGEB)            // 73728

__device__ __forceinline__ uint32_t smem_u32(const void* p){
    uint32_t a;
    asm("{ .reg .u64 t; cvta.to.shared.u64 t, %1; cvt.u32.u64 %0, t; }" : "=r"(a) : "l"(p));
    return a;
}
__device__ __forceinline__ void cp16(uint32_t smem, const void* gmem){
    asm volatile("cp.async.ca.shared.global [%0], [%1], 16;" :: "r"(smem), "l"(gmem));
}
__device__ __forceinline__ void ldsm4(uint32_t r[4], uint32_t addr){
    asm volatile("ldmatrix.sync.aligned.m8n8.x4.shared.b16 {%0,%1,%2,%3}, [%4];"
        : "=r"(r[0]), "=r"(r[1]), "=r"(r[2]), "=r"(r[3]) : "r"(addr));
}
__device__ __forceinline__ void mma_f16(float c[4],
        uint32_t a0, uint32_t a1, uint32_t a2, uint32_t a3,
        uint32_t b0, uint32_t b1){
    asm volatile(
        "mma.sync.aligned.m16n8k16.row.col.f32.f16.f16.f32 "
        "{%0,%1,%2,%3}, {%4,%5,%6,%7}, {%8,%9}, {%0,%1,%2,%3};"
        : "+f"(c[0]), "+f"(c[1]), "+f"(c[2]), "+f"(c[3])
        : "r"(a0), "r"(a1), "r"(a2), "r"(a3), "r"(b0), "r"(b1));
}

// A: [M,ldA] row-major fp16 (K cols used). B: [N,ldB] row-major fp16 (K-major).
__global__ __launch_bounds__(128, 2)
void gemm_f16(const __half* __restrict__ A, const __half* __restrict__ B,
              const float* __restrict__ bias, const float* __restrict__ res,
              float* __restrict__ Cf, __half* __restrict__ Ch,
              int K, int ldA, int ldB, int ldC,
              long long sA, long long sB, long long sC, float alpha)
{
    extern __shared__ __align__(128) char smem[];
    const uint32_t sbase = smem_u32(smem);

    A += (size_t)blockIdx.z * sA;
    B += (size_t)blockIdx.z * sB;
    if (Cf) Cf += (size_t)blockIdx.z * sC;
    if (Ch) Ch += (size_t)blockIdx.z * sC;

    const int tid  = threadIdx.x;
    const int lane = tid & 31;
    const int warp = tid >> 5;      // 0..3
    const int g    = lane >> 2;
    const int tg   = lane & 3;
    const int wm   = warp & 1;      // 2 warps on M (64 rows each)
    const int wn   = warp >> 1;     // 2 warps on N (64 cols each)
    const int m0   = blockIdx.y * BMH;
    const int n0   = blockIdx.x * BNH;
    const int NK   = K / BKH;

    float acc[4][8][4] = {};        // mt(4 x 16 rows) x nt(8 x 8 cols) x 4

    // ---- fill addressing: 128 threads, pointer-stepped ----
    const int fr = tid >> 3;            // 0..15 base row
    const int fc = tid & 7;             // 16B column group
    const __half* gA = A + (size_t)(m0 + fr) * ldA + fc * 8;
    const __half* gB = B + (size_t)(n0 + fr) * ldB + fc * 8;
    const int aStep = 16 * ldA;
    const int bStep = 16 * ldB;
    const uint32_t dA0 = sbase + fr * ROWB + fc * 16;
    const uint32_t dB0 = dA0 + TILEB;

    auto fill = [&](int buf){
        const uint32_t off = buf ? STAGEB : 0u;
        #pragma unroll
        for (int i = 0; i < 8; i++)
            cp16(dA0 + off + i * (16 * ROWB), gA + (size_t)i * aStep);
        #pragma unroll
        for (int i = 0; i < 8; i++)
            cp16(dB0 + off + i * (16 * ROWB), gB + (size_t)i * bStep);
        asm volatile("cp.async.commit_group;");
        gA += BKH; gB += BKH;
    };

    // ---- ldmatrix base offsets ----
    const uint32_t aOff = (uint32_t)((wm * 64 + (lane & 15)) * ROWB + ((lane >> 4) * 16));
    const uint32_t bOff = (uint32_t)(TILEB + (wn * 64 + (lane & 15)) * ROWB + ((lane >> 4) * 16));

    fill(0);

    for (int kt = 0; kt < NK; kt++){
        asm volatile("cp.async.wait_group 0;");
        __syncthreads();
        if (kt + 1 < NK) fill((kt + 1) & 1);

        const uint32_t sb = sbase + (kt & 1 ? STAGEB : 0u);
        const uint32_t aB = sb + aOff;
        const uint32_t bB = sb + bOff;

        // intra-kt fragment double buffer: prefetch ks+1 while computing ks
        uint32_t af[2][4][4], bf[2][4][4];
        #pragma unroll
        for (int mt = 0; mt < 4; mt++)
            ldsm4(af[0][mt], aB + mt * (16 * ROWB));
        #pragma unroll
        for (int pr = 0; pr < 4; pr++)
            ldsm4(bf[0][pr], bB + pr * (16 * ROWB));

        #pragma unroll
        for (int ks = 0; ks < 4; ks++){
            const int cur = ks & 1, nxt = cur ^ 1;
            if (ks < 3){
                #pragma unroll
                for (int mt = 0; mt < 4; mt++)
                    ldsm4(af[nxt][mt], aB + mt * (16 * ROWB) + (ks + 1) * 32);
                #pragma unroll
                for (int pr = 0; pr < 4; pr++)
                    ldsm4(bf[nxt][pr], bB + pr * (16 * ROWB) + (ks + 1) * 32);
            }
            #pragma unroll
            for (int pr = 0; pr < 4; pr++){
                #pragma unroll
                for (int mt = 0; mt < 4; mt++){
                    mma_f16(acc[mt][2*pr  ], af[cur][mt][0], af[cur][mt][1], af[cur][mt][2], af[cur][mt][3], bf[cur][pr][0], bf[cur][pr][2]);
                    mma_f16(acc[mt][2*pr+1], af[cur][mt][0], af[cur][mt][1], af[cur][mt][2], af[cur][mt][3], bf[cur][pr][1], bf[cur][pr][3]);
                }
            }
        }
    }

    // epilogue: warp covers rows [wm*64, +64), cols [wn*64, +64)
    #pragma unroll
    for (int mt = 0; mt < 4; mt++){
        #pragma unroll
        for (int nt = 0; nt < 8; nt++){
            int row = m0 + wm * 64 + mt * 16 + g;
            int col = n0 + wn * 64 + nt * 8 + tg * 2;
            float2 v0 = make_float2(acc[mt][nt][0] * alpha, acc[mt][nt][1] * alpha);
            float2 v1 = make_float2(acc[mt][nt][2] * alpha, acc[mt][nt][3] * alpha);
            if (bias){
                float2 bb = *(const float2*)(bias + col);
                v0.x += bb.x; v0.y += bb.y; v1.x += bb.x; v1.y += bb.y;
            }
            if (res){
                float2 r0 = *(const float2*)(res + (size_t)row * ldC + col);
                float2 r1 = *(const float2*)(res + (size_t)(row + 8) * ldC + col);
                v0.x += r0.x; v0.y += r0.y; v1.x += r1.x; v1.y += r1.y;
            }
            if (Cf){
                *(float2*)(Cf + (size_t)row * ldC + col) = v0;
                *(float2*)(Cf + (size_t)(row + 8) * ldC + col) = v1;
            }
            if (Ch){
                *(__half2*)(Ch + (size_t)row * ldC + col) = __floats2half2_rn(v0.x, v0.y);
                *(__half2*)(Ch + (size_t)(row + 8) * ldC + col) = __floats2half2_rn(v1.x, v1.y);
            }
        }
    }
}

// ---------------- conversions ----------------
__global__ __launch_bounds__(256)
void f32_to_f16(const float4* __restrict__ in, __half2* __restrict__ out, int n4)
{
    int i = blockIdx.x * 256 + threadIdx.x;
    if (i >= n4) return;
    float4 v = in[i];
    out[2*i]   = __floats2half2_rn(v.x, v.y);
    out[2*i+1] = __floats2half2_rn(v.z, v.w);
}

__global__ __launch_bounds__(256)
void transpose4_w(const float* __restrict__ W0, const float* __restrict__ W1,
                  const float* __restrict__ W2, const float* __restrict__ W3,
                  __half* __restrict__ outT)
{
    __shared__ float t[32][33];
    const float* in = (blockIdx.z == 0) ? W0 : (blockIdx.z == 1) ? W1
                    : (blockIdx.z == 2) ? W2 : W3;
    __half* o = outT + (size_t)blockIdx.z * HH * HH;
    const int c0 = blockIdx.x * 32, r0 = blockIdx.y * 32;
    const int tx = threadIdx.x & 31, ty = threadIdx.x >> 5;
    #pragma unroll
    for (int i = 0; i < 4; i++)
        t[ty + 8*i][tx] = in[(size_t)(r0 + ty + 8*i) * HH + c0 + tx];
    __syncthreads();
    #pragma unroll
    for (int i = 0; i < 4; i++)
        o[(size_t)(c0 + ty + 8*i) * HH + r0 + tx] = __float2half(t[tx][ty + 8*i]);
}

__global__ __launch_bounds__(256)
void transpose_f16(const __half* __restrict__ in, __half* __restrict__ outT,
                   int R, int C, int ldIn, long long sIn, long long sOut)
{
    __shared__ __half t[32][34];
    in   += (size_t)blockIdx.z * sIn;
    outT += (size_t)blockIdx.z * sOut;
    const int c0 = blockIdx.x * 32, r0 = blockIdx.y * 32;
    const int tx = threadIdx.x & 31, ty = threadIdx.x >> 5;
    #pragma unroll
    for (int i = 0; i < 4; i++)
        t[ty + 8*i][tx] = in[(size_t)(r0 + ty + 8*i) * ldIn + c0 + tx];
    __syncthreads();
    #pragma unroll
    for (int i = 0; i < 4; i++)
        outT[(size_t)(c0 + ty + 8*i) * R + r0 + tx] = t[tx][ty + 8*i];
}

__global__ void concat_bias(const float* __restrict__ a, const float* __restrict__ b,
                            const float* __restrict__ c, float* __restrict__ out)
{
    int i = blockIdx.x * 256 + threadIdx.x;
    if (i < HH)            out[i] = a[i];
    else if (i < 2*HH)     out[i] = b[i - HH];
    else if (i < 3*HH)     out[i] = c[i - 2*HH];
}

// ---------------- XSoftmax fp16 in-place ----------------
__global__ __launch_bounds__(256)
void xsoftmax_f16(__half* __restrict__ sc, const int* __restrict__ mask)
{
    const int b = blockIdx.y;
    const int s = blockIdx.x;
    __half* row = sc + ((size_t)b * SS + s) * SS;
    const int* mrow = mask + (size_t)b * SS;
    const int tid = threadIdx.x;

    uint4 raw = ((const uint4*)row)[tid];
    __half2 hx[4];
    hx[0] = *(__half2*)&raw.x; hx[1] = *(__half2*)&raw.y;
    hx[2] = *(__half2*)&raw.z; hx[3] = *(__half2*)&raw.w;
    int4 ma = ((const int4*)mrow)[2*tid];
    int4 mb = ((const int4*)mrow)[2*tid + 1];
    int m[8] = {ma.x, ma.y, ma.z, ma.w, mb.x, mb.y, mb.z, mb.w};

    const float NEG = -3.402823466e38f;
    float x[8];
    float mx = NEG;
    #pragma unroll
    for (int j = 0; j < 4; j++){
        float2 f = __half22float2(hx[j]);
        x[2*j]   = m[2*j]   ? f.x : NEG;
        x[2*j+1] = m[2*j+1] ? f.y : NEG;
        mx = fmaxf(mx, fmaxf(x[2*j], x[2*j+1]));
    }

    __shared__ float red[256];
    red[tid] = mx; __syncthreads();
    for (int off = 128; off > 0; off >>= 1){
        if (tid < off) red[tid] = fmaxf(red[tid], red[tid + off]);
        __syncthreads();
    }
    mx = red[0]; __syncthreads();

    float sum = 0.f;
    #pragma unroll
    for (int j = 0; j < 8; j++){ float e = __expf(x[j] - mx); x[j] = e; sum += e; }
    red[tid] = sum; __syncthreads();
    for (int off = 128; off > 0; off >>= 1){
        if (tid < off) red[tid] += red[tid + off];
        __syncthreads();
    }
    const float inv = 1.0f / red[0];

    #pragma unroll
    for (int j = 0; j < 4; j++){
        float p0 = m[2*j]   ? x[2*j]   * inv : 0.0f;
        float p1 = m[2*j+1] ? x[2*j+1] * inv : 0.0f;
        hx[j] = __floats2half2_rn(p0, p1);
    }
    raw.x = *(uint32_t*)&hx[0]; raw.y = *(uint32_t*)&hx[1];
    raw.z = *(uint32_t*)&hx[2]; raw.w = *(uint32_t*)&hx[3];
    ((uint4*)row)[tid] = raw;
}

// ---------------- LayerNorm ----------------
__global__ __launch_bounds__(256)
void layernorm_kernel(const float* __restrict__ h, const float* __restrict__ gamma,
                      const float* __restrict__ beta, float* __restrict__ out)
{
    const int row = blockIdx.x;
    const float* r = h + (size_t)row * HH;
    float* o = out + (size_t)row * HH;
    const int tid = threadIdx.x;

    float v0 = r[tid], v1 = r[tid + 256], v2 = r[tid + 512];
    float s = v0 + v1 + v2;
    float ss = v0*v0 + v1*v1 + v2*v2;

    __shared__ float rs[256], rss[256];
    rs[tid] = s; rss[tid] = ss; __syncthreads();
    for (int off = 128; off > 0; off >>= 1){
        if (tid < off){ rs[tid] += rs[tid + off]; rss[tid] += rss[tid + off]; }
        __syncthreads();
    }
    const float mu = rs[0] * (1.0f / HH);
    const float var = rss[0] * (1.0f / HH) - mu * mu;
    const float rstd = rsqrtf(var + 1e-12f);

    o[tid]       = (v0 - mu) * rstd * gamma[tid]       + beta[tid];
    o[tid + 256] = (v1 - mu) * rstd * gamma[tid + 256] + beta[tid + 256];
    o[tid + 512] = (v2 - mu) * rstd * gamma[tid + 512] + beta[tid + 512];
}

// ---------------- host ----------------
extern "C" void kernel_launch(void* const* d_in, const int* in_sizes, int n_in,
                              void* d_out, int out_size)
{
    const float* X     = (const float*)d_in[0];
    const int*   mask  = (const int*)  d_in[1];
    const float* Wq    = (const float*)d_in[2];
    const float* bq    = (const float*)d_in[3];
    const float* Wk    = (const float*)d_in[4];
    const float* bk    = (const float*)d_in[5];
    const float* Wv    = (const float*)d_in[6];
    const float* bv    = (const float*)d_in[7];
    const float* Wo    = (const float*)d_in[8];
    const float* bo    = (const float*)d_in[9];
    const float* gamma = (const float*)d_in[10];
    const float* beta  = (const float*)d_in[11];
    float* out = (float*)d_out;

    __half *xh, *wt, *qkv, *vt, *sc, *ch;
    float *bqkv, *h;
    cudaGetSymbolAddress((void**)&xh,   g_xh);
    cudaGetSymbolAddress((void**)&wt,   g_wt);
    cudaGetSymbolAddress((void**)&bqkv, g_bqkv);
    cudaGetSymbolAddress((void**)&qkv,  g_qkv);
    cudaGetSymbolAddress((void**)&vt,   g_vt);
    cudaGetSymbolAddress((void**)&sc,   g_sc);
    cudaGetSymbolAddress((void**)&ch,   g_ch);
    cudaGetSymbolAddress((void**)&h,    g_h);

    static int smemSet = 0;
    if (!smemSet){
        cudaFuncSetAttribute(gemm_f16, cudaFuncAttributeMaxDynamicSharedMemorySize, GSMEM);
        smemSet = 1;
    }

    const dim3 blkG(128);
    const dim3 blk(256);
    const size_t WW = (size_t)HH * HH;

    // 0) conversions
    {
        int n4 = MTOT * HH / 4;
        f32_to_f16<<<(n4 + 255)/256, blk>>>((const float4*)X, (__half2*)xh, n4);
        dim3 tg(HH/32, HH/32, 4);
        transpose4_w<<<tg, blk>>>(Wq, Wk, Wv, Wo, wt);
        concat_bias<<<(NQKV + 255)/256, blk>>>(bq, bk, bv, bqkv);
    }

    // 1) fused QKV
    {
        dim3 grid(NQKV/BNH, MTOT/BMH, 1);
        gemm_f16<<<grid, blkG, GSMEM>>>(xh, wt, bqkv, nullptr, nullptr, qkv,
                                        HH, HH, HH, NQKV, 0, 0, 0, 1.0f);
    }

    // 1b) v -> v^T per batch
    {
        dim3 tg(HH/32, SS/32, BB);
        transpose_f16<<<tg, blk>>>(qkv + 2*HH, vt, SS, HH, NQKV,
                                   (long long)SS*NQKV, (long long)HH*SS);
    }

    // 2) scores = q @ k^T / sqrt(H) -> fp16
    {
        dim3 grid(SS/BNH, SS/BMH, BB);
        gemm_f16<<<grid, blkG, GSMEM>>>(qkv, qkv + HH, nullptr, nullptr, nullptr, sc,
                                        HH, NQKV, NQKV, SS,
                                        (long long)SS*NQKV, (long long)SS*NQKV,
                                        (long long)SS*SS, 1.0f/sqrtf((float)HH));
    }

    // 3) masked softmax in-place
    {
        dim3 grid(SS, BB, 1);
        xsoftmax_f16<<<grid, blk>>>(sc, mask);
    }

    // 4) ctx = probs @ v -> fp16
    {
        dim3 grid(HH/BNH, SS/BMH, BB);
        gemm_f16<<<grid, blkG, GSMEM>>>(sc, vt, nullptr, nullptr, nullptr, ch,
                                        SS, SS, SS, HH,
                                        (long long)SS*SS, (long long)HH*SS,
                                        (long long)SS*HH, 1.0f);
    }

    // 5) h = ctx @ Wo + bo + X -> fp32
    {
        dim3 grid(HH/BNH, MTOT/BMH, 1);
        gemm_f16<<<grid, blkG, GSMEM>>>(ch, wt + 3*WW, bo, X, h, nullptr,
                                        HH, HH, HH, HH, 0, 0, 0, 1.0f);
    }

    // 6) LayerNorm -> out
    {
        dim3 grid(MTOT, 1, 1);
        layernorm_kernel<<<grid, blk>>>(h, gamma, beta, out);
    }
}

// round 11
// speedup vs baseline: 1.6736x; 1.0801x over previous
#include <cuda_runtime.h>
#include <cuda_fp16.h>
#include <math.h>
#include <stdint.h>

#define BB 8
#define SS 2048
#define HH 768
#define MTOT (BB*SS)   // 16384
#define NQKV 2304      // 3*HH

// ---------------- scratch (device globals) ----------------
__device__ __half g_xh[MTOT*HH];
__device__ __half g_wt[4*HH*HH];                 // W^T fp16
__device__ float  g_bqkv[NQKV];
__device__ __half g_qkv[(size_t)MTOT*NQKV];      // q | k | v packed per row
__device__ __half g_sc[(size_t)BB*SS*SS];        // fp16 scores -> probs in-place
__device__ __half g_ch[MTOT*HH];
__device__ float  g_h[MTOT*HH];

// ---------------- fp16 tensor-core GEMM ----------------
// CTA tile 128x128x64, 128 threads = 4 warps, warp tile 64x64.
// TRANSB=true : NT, B is [N][K] row-major (K-major)   -> plain ldmatrix
// TRANSB=false: NN, B is [K][N] row-major             -> ldmatrix.trans
#define BMH 128
#define BNH 128
#define BKH 64
#define ROWB 144                    // A/B-NT: 64 halfs = 128B -> pad to 144B
#define RBN  272                    // B-NN: 128 halfs = 256B -> pad to 272B
#define TILEB (BMH*ROWB)            // 18432 (A tile; also B-NT tile; >= B-NN 64*272=17408)
#define STAGEB (2*TILEB)            // 36864
#define GSMEM (2*STAGEB)            // 73728

__device__ __forceinline__ uint32_t smem_u32(const void* p){
    uint32_t a;
    asm("{ .reg .u64 t; cvta.to.shared.u64 t, %1; cvt.u32.u64 %0, t; }" : "=r"(a) : "l"(p));
    return a;
}
__device__ __forceinline__ void cp16(uint32_t smem, const void* gmem){
    asm volatile("cp.async.ca.shared.global [%0], [%1], 16;" :: "r"(smem), "l"(gmem));
}
__device__ __forceinline__ void ldsm4(uint32_t r[4], uint32_t addr){
    asm volatile("ldmatrix.sync.aligned.m8n8.x4.shared.b16 {%0,%1,%2,%3}, [%4];"
        : "=r"(r[0]), "=r"(r[1]), "=r"(r[2]), "=r"(r[3]) : "r"(addr));
}
__device__ __forceinline__ void ldsm4t(uint32_t r[4], uint32_t addr){
    asm volatile("ldmatrix.sync.aligned.m8n8.x4.trans.shared.b16 {%0,%1,%2,%3}, [%4];"
        : "=r"(r[0]), "=r"(r[1]), "=r"(r[2]), "=r"(r[3]) : "r"(addr));
}
__device__ __forceinline__ void mma_f16(float c[4],
        uint32_t a0, uint32_t a1, uint32_t a2, uint32_t a3,
        uint32_t b0, uint32_t b1){
    asm volatile(
        "mma.sync.aligned.m16n8k16.row.col.f32.f16.f16.f32 "
        "{%0,%1,%2,%3}, {%4,%5,%6,%7}, {%8,%9}, {%0,%1,%2,%3};"
        : "+f"(c[0]), "+f"(c[1]), "+f"(c[2]), "+f"(c[3])
        : "r"(a0), "r"(a1), "r"(a2), "r"(a3), "r"(b0), "r"(b1));
}

// A: [M,ldA] row-major fp16 (K cols used).
// B: TRANSB ? [N,ldB] : [K,ldB] row-major fp16.
template<bool TRANSB>
__global__ __launch_bounds__(128, 2)
void gemm_f16(const __half* __restrict__ A, const __half* __restrict__ B,
              const float* __restrict__ bias, const float* __restrict__ res,
              float* __restrict__ Cf, __half* __restrict__ Ch,
              int K, int ldA, int ldB, int ldC,
              long long sA, long long sB, long long sC, float alpha)
{
    extern __shared__ __align__(128) char smem[];
    const uint32_t sbase = smem_u32(smem);

    A += (size_t)blockIdx.z * sA;
    B += (size_t)blockIdx.z * sB;
    if (Cf) Cf += (size_t)blockIdx.z * sC;
    if (Ch) Ch += (size_t)blockIdx.z * sC;

    const int tid  = threadIdx.x;
    const int lane = tid & 31;
    const int warp = tid >> 5;      // 0..3
    const int g    = lane >> 2;
    const int tg   = lane & 3;
    const int wm   = warp & 1;      // 2 warps on M (64 rows each)
    const int wn   = warp >> 1;     // 2 warps on N (64 cols each)
    const int m0   = blockIdx.y * BMH;
    const int n0   = blockIdx.x * BNH;
    const int NK   = K / BKH;

    float acc[4][8][4] = {};

    // ---- A fill addressing (shared by both modes) ----
    const int fr = tid >> 3;            // 0..15
    const int fc = tid & 7;             // 16B chunk
    const __half* gA = A + (size_t)(m0 + fr) * ldA + fc * 8;
    const int aStep = 16 * ldA;
    const uint32_t dA0 = sbase + fr * ROWB + fc * 16;

    // ---- B fill addressing ----
    // NT: 128 rows (n) x 64 halfs; NN: 64 rows (k) x 128 halfs
    const int fr2 = tid >> 4;           // 0..7  (NN)
    const int fc2 = tid & 15;           // 16B chunk (NN)
    const __half* gB = TRANSB ? (B + (size_t)(n0 + fr) * ldB + fc * 8)
                              : (B + (size_t)fr2 * ldB + n0 + fc2 * 8);
    const int bStep  = TRANSB ? 16 * ldB : 8 * ldB;
    const uint32_t dB0 = TRANSB ? (dA0 + TILEB)
                                : (sbase + TILEB + fr2 * RBN + fc2 * 16);

    auto fill = [&](int buf){
        const uint32_t off = buf ? STAGEB : 0u;
        #pragma unroll
        for (int i = 0; i < 8; i++)
            cp16(dA0 + off + i * (16 * ROWB), gA + (size_t)i * aStep);
        if (TRANSB){
            #pragma unroll
            for (int i = 0; i < 8; i++)
                cp16(dB0 + off + i * (16 * ROWB), gB + (size_t)i * bStep);
        } else {
            #pragma unroll
            for (int i = 0; i < 8; i++)
                cp16(dB0 + off + i * (8 * RBN), gB + (size_t)i * bStep);
        }
        asm volatile("cp.async.commit_group;");
        gA += BKH;
        gB += TRANSB ? BKH : (size_t)BKH * ldB;
    };

    // ---- ldmatrix base offsets ----
    const uint32_t aOff = (uint32_t)((wm * 64 + (lane & 15)) * ROWB + ((lane >> 4) * 16));
    // NT: rows = n, 16B chunk = k halves
    const uint32_t bOffNT = (uint32_t)(TILEB + (wn * 64 + (lane & 15)) * ROWB + ((lane >> 4) * 16));
    // NN trans: matrix j from lanes 8j..8j+7; lane -> k-row, n chunk
    const uint32_t bOffNN = (uint32_t)(TILEB + ((lane & 7) + 8 * ((lane >> 3) & 1)) * RBN
                                       + (wn * 64 + (lane >> 4) * 8) * 2);
    const uint32_t bOff = TRANSB ? bOffNT : bOffNN;

    fill(0);

    for (int kt = 0; kt < NK; kt++){
        asm volatile("cp.async.wait_group 0;");
        __syncthreads();
        if (kt + 1 < NK) fill((kt + 1) & 1);

        const uint32_t sb = sbase + (kt & 1 ? STAGEB : 0u);
        const uint32_t aB = sb + aOff;
        const uint32_t bB = sb + bOff;

        #pragma unroll
        for (int ks = 0; ks < 4; ks++){
            uint32_t af[4][4];
            #pragma unroll
            for (int mt = 0; mt < 4; mt++)
                ldsm4(af[mt], aB + mt * (16 * ROWB) + ks * 32);

            uint32_t bf[2][4];
            if (TRANSB) ldsm4 (bf[0], bB + ks * 32);
            else        ldsm4t(bf[0], bB + ks * (16 * RBN));
            #pragma unroll
            for (int pr = 0; pr < 4; pr++){
                const int c = pr & 1;
                if (pr < 3){
                    if (TRANSB) ldsm4 (bf[c ^ 1], bB + (pr + 1) * (16 * ROWB) + ks * 32);
                    else        ldsm4t(bf[c ^ 1], bB + ks * (16 * RBN) + (pr + 1) * 32);
                }
                #pragma unroll
                for (int mt = 0; mt < 4; mt++){
                    if (TRANSB){
                        mma_f16(acc[mt][2*pr  ], af[mt][0], af[mt][1], af[mt][2], af[mt][3], bf[c][0], bf[c][2]);
                        mma_f16(acc[mt][2*pr+1], af[mt][0], af[mt][1], af[mt][2], af[mt][3], bf[c][1], bf[c][3]);
                    } else {
                        mma_f16(acc[mt][2*pr  ], af[mt][0], af[mt][1], af[mt][2], af[mt][3], bf[c][0], bf[c][1]);
                        mma_f16(acc[mt][2*pr+1], af[mt][0], af[mt][1], af[mt][2], af[mt][3], bf[c][2], bf[c][3]);
                    }
                }
            }
        }
    }

    // epilogue
    #pragma unroll
    for (int mt = 0; mt < 4; mt++){
        #pragma unroll
        for (int nt = 0; nt < 8; nt++){
            int row = m0 + wm * 64 + mt * 16 + g;
            int col = n0 + wn * 64 + nt * 8 + tg * 2;
            float2 v0 = make_float2(acc[mt][nt][0] * alpha, acc[mt][nt][1] * alpha);
            float2 v1 = make_float2(acc[mt][nt][2] * alpha, acc[mt][nt][3] * alpha);
            if (bias){
                float2 bb = *(const float2*)(bias + col);
                v0.x += bb.x; v0.y += bb.y; v1.x += bb.x; v1.y += bb.y;
            }
            if (res){
                float2 r0 = *(const float2*)(res + (size_t)row * ldC + col);
                float2 r1 = *(const float2*)(res + (size_t)(row + 8) * ldC + col);
                v0.x += r0.x; v0.y += r0.y; v1.x += r1.x; v1.y += r1.y;
            }
            if (Cf){
                *(float2*)(Cf + (size_t)row * ldC + col) = v0;
                *(float2*)(Cf + (size_t)(row + 8) * ldC + col) = v1;
            }
            if (Ch){
                *(__half2*)(Ch + (size_t)row * ldC + col) = __floats2half2_rn(v0.x, v0.y);
                *(__half2*)(Ch + (size_t)(row + 8) * ldC + col) = __floats2half2_rn(v1.x, v1.y);
            }
        }
    }
}

// ---------------- conversions ----------------
__global__ __launch_bounds__(256)
void f32_to_f16(const float4* __restrict__ in, __half2* __restrict__ out, int n4)
{
    int i = blockIdx.x * 256 + threadIdx.x;
    if (i >= n4) return;
    float4 v = in[i];
    out[2*i]   = __floats2half2_rn(v.x, v.y);
    out[2*i+1] = __floats2half2_rn(v.z, v.w);
}

__global__ __launch_bounds__(256)
void transpose4_w(const float* __restrict__ W0, const float* __restrict__ W1,
                  const float* __restrict__ W2, const float* __restrict__ W3,
                  __half* __restrict__ outT)
{
    __shared__ float t[32][33];
    const float* in = (blockIdx.z == 0) ? W0 : (blockIdx.z == 1) ? W1
                    : (blockIdx.z == 2) ? W2 : W3;
    __half* o = outT + (size_t)blockIdx.z * HH * HH;
    const int c0 = blockIdx.x * 32, r0 = blockIdx.y * 32;
    const int tx = threadIdx.x & 31, ty = threadIdx.x >> 5;
    #pragma unroll
    for (int i = 0; i < 4; i++)
        t[ty + 8*i][tx] = in[(size_t)(r0 + ty + 8*i) * HH + c0 + tx];
    __syncthreads();
    #pragma unroll
    for (int i = 0; i < 4; i++)
        o[(size_t)(c0 + ty + 8*i) * HH + r0 + tx] = __float2half(t[tx][ty + 8*i]);
}

__global__ void concat_bias(const float* __restrict__ a, const float* __restrict__ b,
                            const float* __restrict__ c, float* __restrict__ out)
{
    int i = blockIdx.x * 256 + threadIdx.x;
    if (i < HH)            out[i] = a[i];
    else if (i < 2*HH)     out[i] = b[i - HH];
    else if (i < 3*HH)     out[i] = c[i - 2*HH];
}

// ---------------- XSoftmax fp16 in-place (2-barrier shuffle reduction) ----------------
__global__ __launch_bounds__(256)
void xsoftmax_f16(__half* __restrict__ sc, const int* __restrict__ mask)
{
    const int b = blockIdx.y;
    const int s = blockIdx.x;
    __half* row = sc + ((size_t)b * SS + s) * SS;
    const int* mrow = mask + (size_t)b * SS;
    const int tid  = threadIdx.x;
    const int lane = tid & 31;
    const int wid  = tid >> 5;

    uint4 raw = ((const uint4*)row)[tid];
    __half2 hx[4];
    hx[0] = *(__half2*)&raw.x; hx[1] = *(__half2*)&raw.y;
    hx[2] = *(__half2*)&raw.z; hx[3] = *(__half2*)&raw.w;
    int4 ma = ((const int4*)mrow)[2*tid];
    int4 mb = ((const int4*)mrow)[2*tid + 1];
    int m[8] = {ma.x, ma.y, ma.z, ma.w, mb.x, mb.y, mb.z, mb.w};

    const float NEG = -3.402823466e38f;
    float x[8];
    float mx = NEG;
    #pragma unroll
    for (int j = 0; j < 4; j++){
        float2 f = __half22float2(hx[j]);
        x[2*j]   = m[2*j]   ? f.x : NEG;
        x[2*j+1] = m[2*j+1] ? f.y : NEG;
        mx = fmaxf(mx, fmaxf(x[2*j], x[2*j+1]));
    }

    __shared__ float redM[8], redS[8];
    #pragma unroll
    for (int o = 16; o > 0; o >>= 1)
        mx = fmaxf(mx, __shfl_xor_sync(0xFFFFFFFFu, mx, o));
    if (lane == 0) redM[wid] = mx;
    __syncthreads();
    mx = redM[0];
    #pragma unroll
    for (int w = 1; w < 8; w++) mx = fmaxf(mx, redM[w]);

    float sum = 0.f;
    #pragma unroll
    for (int j = 0; j < 8; j++){ float e = __expf(x[j] - mx); x[j] = e; sum += e; }
    #pragma unroll
    for (int o = 16; o > 0; o >>= 1)
        sum += __shfl_xor_sync(0xFFFFFFFFu, sum, o);
    if (lane == 0) redS[wid] = sum;
    __syncthreads();
    sum = redS[0];
    #pragma unroll
    for (int w = 1; w < 8; w++) sum += redS[w];
    const float inv = 1.0f / sum;

    #pragma unroll
    for (int j = 0; j < 4; j++){
        float p0 = m[2*j]   ? x[2*j]   * inv : 0.0f;
        float p1 = m[2*j+1] ? x[2*j+1] * inv : 0.0f;
        hx[j] = __floats2half2_rn(p0, p1);
    }
    raw.x = *(uint32_t*)&hx[0]; raw.y = *(uint32_t*)&hx[1];
    raw.z = *(uint32_t*)&hx[2]; raw.w = *(uint32_t*)&hx[3];
    ((uint4*)row)[tid] = raw;
}

// ---------------- LayerNorm (float4 + shuffle, 192 thr/row) ----------------
__global__ __launch_bounds__(192)
void layernorm_kernel(const float* __restrict__ h, const float* __restrict__ gamma,
                      const float* __restrict__ beta, float* __restrict__ out)
{
    const int row = blockIdx.x;
    const int tid  = threadIdx.x;
    const int lane = tid & 31;
    const int wid  = tid >> 5;      // 0..5

    float4 v = ((const float4*)(h + (size_t)row * HH))[tid];
    float s  = v.x + v.y + v.z + v.w;
    float ss = v.x*v.x + v.y*v.y + v.z*v.z + v.w*v.w;

    #pragma unroll
    for (int o = 16; o > 0; o >>= 1){
        s  += __shfl_xor_sync(0xFFFFFFFFu, s,  o);
        ss += __shfl_xor_sync(0xFFFFFFFFu, ss, o);
    }
    __shared__ float2 red[6];
    if (lane == 0) red[wid] = make_float2(s, ss);
    __syncthreads();
    s = 0.f; ss = 0.f;
    #pragma unroll
    for (int w = 0; w < 6; w++){ s += red[w].x; ss += red[w].y; }

    const float mu  = s * (1.0f / HH);
    const float var = ss * (1.0f / HH) - mu * mu;
    const float rstd = rsqrtf(var + 1e-12f);

    float4 gm = ((const float4*)gamma)[tid];
    float4 bt = ((const float4*)beta)[tid];
    float4 o4;
    o4.x = (v.x - mu) * rstd * gm.x + bt.x;
    o4.y = (v.y - mu) * rstd * gm.y + bt.y;
    o4.z = (v.z - mu) * rstd * gm.z + bt.z;
    o4.w = (v.w - mu) * rstd * gm.w + bt.w;
    ((float4*)(out + (size_t)row * HH))[tid] = o4;
}

// ---------------- host ----------------
extern "C" void kernel_launch(void* const* d_in, const int* in_sizes, int n_in,
                              void* d_out, int out_size)
{
    const float* X     = (const float*)d_in[0];
    const int*   mask  = (const int*)  d_in[1];
    const float* Wq    = (const float*)d_in[2];
    const float* bq    = (const float*)d_in[3];
    const float* Wk    = (const float*)d_in[4];
    const float* bk    = (const float*)d_in[5];
    const float* Wv    = (const float*)d_in[6];
    const float* bv    = (const float*)d_in[7];
    const float* Wo    = (const float*)d_in[8];
    const float* bo    = (const float*)d_in[9];
    const float* gamma = (const float*)d_in[10];
    const float* beta  = (const float*)d_in[11];
    float* out = (float*)d_out;

    __half *xh, *wt, *qkv, *sc, *ch;
    float *bqkv, *h;
    cudaGetSymbolAddress((void**)&xh,   g_xh);
    cudaGetSymbolAddress((void**)&wt,   g_wt);
    cudaGetSymbolAddress((void**)&bqkv, g_bqkv);
    cudaGetSymbolAddress((void**)&qkv,  g_qkv);
    cudaGetSymbolAddress((void**)&sc,   g_sc);
    cudaGetSymbolAddress((void**)&ch,   g_ch);
    cudaGetSymbolAddress((void**)&h,    g_h);

    static int smemSet = 0;
    if (!smemSet){
        cudaFuncSetAttribute(gemm_f16<true>,  cudaFuncAttributeMaxDynamicSharedMemorySize, GSMEM);
        cudaFuncSetAttribute(gemm_f16<false>, cudaFuncAttributeMaxDynamicSharedMemorySize, GSMEM);
        smemSet = 1;
    }

    const dim3 blkG(128);
    const dim3 blk(256);
    const size_t WW = (size_t)HH * HH;

    // 0) conversions
    {
        int n4 = MTOT * HH / 4;
        f32_to_f16<<<(n4 + 255)/256, blk>>>((const float4*)X, (__half2*)xh, n4);
        dim3 tg(HH/32, HH/32, 4);
        transpose4_w<<<tg, blk>>>(Wq, Wk, Wv, Wo, wt);
        concat_bias<<<(NQKV + 255)/256, blk>>>(bq, bk, bv, bqkv);
    }

    // 1) fused QKV
    {
        dim3 grid(NQKV/BNH, MTOT/BMH, 1);
        gemm_f16<true><<<grid, blkG, GSMEM>>>(xh, wt, bqkv, nullptr, nullptr, qkv,
                                              HH, HH, HH, NQKV, 0, 0, 0, 1.0f);
    }

    // 2) scores = q @ k^T / sqrt(H) -> fp16
    {
        dim3 grid(SS/BNH, SS/BMH, BB);
        gemm_f16<true><<<grid, blkG, GSMEM>>>(qkv, qkv + HH, nullptr, nullptr, nullptr, sc,
                                              HH, NQKV, NQKV, SS,
                                              (long long)SS*NQKV, (long long)SS*NQKV,
                                              (long long)SS*SS, 1.0f/sqrtf((float)HH));
    }

    // 3) masked softmax in-place
    {
        dim3 grid(SS, BB, 1);
        xsoftmax_f16<<<grid, blk>>>(sc, mask);
    }

    // 4) ctx = probs @ v -> fp16   (NN mode: v read directly, no transpose)
    {
        dim3 grid(HH/BNH, SS/BMH, BB);
        gemm_f16<false><<<grid, blkG, GSMEM>>>(sc, qkv + 2*HH, nullptr, nullptr, nullptr, ch,
                                               SS, SS, NQKV, HH,
                                               (long long)SS*SS, (long long)SS*NQKV,
                                               (long long)SS*HH, 1.0f);
    }

    // 5) h = ctx @ Wo + bo + X -> fp32
    {
        dim3 grid(HH/BNH, MTOT/BMH, 1);
        gemm_f16<true><<<grid, blkG, GSMEM>>>(ch, wt + 3*WW, bo, X, h, nullptr,
                                              HH, HH, HH, HH, 0, 0, 0, 1.0f);
    }

    // 6) LayerNorm -> out
    {
        dim3 grid(MTOT, 1, 1);
        layernorm_kernel<<<grid, dim3(192)>>>(h, gamma, beta, out);
    }
}